// round 4
// baseline (speedup 1.0000x reference)
#include <cuda_runtime.h>
#include <cuda_bf16.h>
#include <cstddef>

// ---------------------------------------------------------------------------
// 2-layer TF LSTM: B=32, T=512, INSZ=HSZ=1024, G=4096.
// Inputs: x[32,512,1024] f32, lengths[32] i32, W0[2048,4096], b0[4096],
//         W1[2048,4096], b1[4096].
// Output: concat(out1[32,512,1024], h1[32,1024], c1[32,1024]) f32.
// ---------------------------------------------------------------------------

#define BSZ   32
#define TSTEP 512
#define HS    1024
#define GSZ   4096
#define MROWS (BSZ * TSTEP)      // 16384
#define NBLK  128                // persistent CTAs for recurrence

typedef unsigned long long u64;

// ----------------------------- device scratch ------------------------------
__device__ __align__(16) float g_xproj[(size_t)MROWS * GSZ];  // 256 MB
__device__ __align__(16) float g_out0 [(size_t)MROWS * HS];   //  64 MB
__device__ __align__(16) float g_hbuf [2 * HS * BSZ];         // ping-pong h, [buf][k][b]
__device__ unsigned g_bar;

// ----------------------------- f32x2 helpers -------------------------------
__device__ __forceinline__ u64 pack2(float lo, float hi) {
    u64 r; asm("mov.b64 %0, {%1, %2};" : "=l"(r) : "f"(lo), "f"(hi)); return r;
}
__device__ __forceinline__ void unpack2(u64 v, float& lo, float& hi) {
    asm("mov.b64 {%0, %1}, %2;" : "=f"(lo), "=f"(hi) : "l"(v));
}
__device__ __forceinline__ u64 ffma2(u64 a, u64 b, u64 c) {
    u64 d; asm("fma.rn.f32x2 %0, %1, %2, %3;" : "=l"(d) : "l"(a), "l"(b), "l"(c)); return d;
}
__device__ __forceinline__ u64 add2(u64 a, u64 b) {
    u64 d; asm("add.rn.f32x2 %0, %1, %2;" : "=l"(d) : "l"(a), "l"(b)); return d;
}
__device__ __forceinline__ float sigf(float x) { return 1.0f / (1.0f + __expf(-x)); }

// ----------------------------- barrier reset -------------------------------
__global__ void init_bar_kernel() { g_bar = 0u; }

// ---------------------------------------------------------------------------
// GEMM: C[m][g] = A[m][0:1024] @ W[0:1024][g] + bias[g]
// Tile 128(m) x 64(n), BK=16, 256 thr, microtile 8m x 4n. Double-buffered.
// A stored in SMEM as duplicated f32x2 pairs -> inner loop has zero pack movs:
// 4 LDS.128 (A broadcast) + 1 LDS.128 (B) + 16 FFMA2 per k.
// ---------------------------------------------------------------------------
#define GBM 128
#define GBN 64
#define GBK 16
#define APAD 130    // u64 row stride for Ash

__global__ void __launch_bounds__(256) gemm_kernel(
    const float* __restrict__ A, const float* __restrict__ W,
    const float* __restrict__ bias, float* __restrict__ C)
{
    __shared__ __align__(16) u64   Ash[2][GBK][APAD];  // [k][m] dup pairs
    __shared__ __align__(16) float Bsh[2][GBK][GBN];

    const int tid = threadIdx.x;
    const int m0  = blockIdx.y * GBM;
    const int n0  = blockIdx.x * GBN;
    const int tm  = tid >> 4;          // 0..15 -> rows tm*8..+7
    const int tn  = tid & 15;          // 0..15 -> cols tn*4..+3

    // per-thread load coords
    const int lmA0 = tid >> 2,        lkA0 = (tid & 3) * 4;          // r=0
    const int lmA1 = (tid + 256) >> 2, lkA1 = ((tid + 256) & 3) * 4; // r=1
    const int lkB  = tid >> 4,        lnB  = (tid & 15) * 4;

    u64 acc[8][2];
    {
        ulonglong2 bv = *(const ulonglong2*)(bias + n0 + tn * 4);
#pragma unroll
        for (int i = 0; i < 8; i++) { acc[i][0] = bv.x; acc[i][1] = bv.y; }
    }

    // preload tile 0
    {
        float4 a0 = *(const float4*)(A + (size_t)(m0 + lmA0) * HS + lkA0);
        float4 a1 = *(const float4*)(A + (size_t)(m0 + lmA1) * HS + lkA1);
        float4 bv = *(const float4*)(W + (size_t)lkB * GSZ + n0 + lnB);
        Ash[0][lkA0 + 0][lmA0] = pack2(a0.x, a0.x);
        Ash[0][lkA0 + 1][lmA0] = pack2(a0.y, a0.y);
        Ash[0][lkA0 + 2][lmA0] = pack2(a0.z, a0.z);
        Ash[0][lkA0 + 3][lmA0] = pack2(a0.w, a0.w);
        Ash[0][lkA1 + 0][lmA1] = pack2(a1.x, a1.x);
        Ash[0][lkA1 + 1][lmA1] = pack2(a1.y, a1.y);
        Ash[0][lkA1 + 2][lmA1] = pack2(a1.z, a1.z);
        Ash[0][lkA1 + 3][lmA1] = pack2(a1.w, a1.w);
        *(float4*)&Bsh[0][lkB][lnB] = bv;
    }
    __syncthreads();

    int s = 0;
    for (int it = 0; it < HS / GBK; it++) {
        float4 pa0, pa1, pb;
        const bool more = (it < HS / GBK - 1);
        if (more) {
            int k0 = (it + 1) * GBK;
            pa0 = *(const float4*)(A + (size_t)(m0 + lmA0) * HS + k0 + lkA0);
            pa1 = *(const float4*)(A + (size_t)(m0 + lmA1) * HS + k0 + lkA1);
            pb  = *(const float4*)(W + (size_t)(k0 + lkB) * GSZ + n0 + lnB);
        }

#pragma unroll
        for (int kk = 0; kk < GBK; kk++) {
            const ulonglong2* Ar = (const ulonglong2*)&Ash[s][kk][tm * 8];
            ulonglong2 a01 = Ar[0], a23 = Ar[1], a45 = Ar[2], a67 = Ar[3];
            ulonglong2 wv  = *(const ulonglong2*)&Bsh[s][kk][tn * 4];
            u64 am[8] = {a01.x, a01.y, a23.x, a23.y, a45.x, a45.y, a67.x, a67.y};
#pragma unroll
            for (int i = 0; i < 8; i++) {
                acc[i][0] = ffma2(am[i], wv.x, acc[i][0]);
                acc[i][1] = ffma2(am[i], wv.y, acc[i][1]);
            }
        }

        if (more) {
            int s2 = s ^ 1;
            Ash[s2][lkA0 + 0][lmA0] = pack2(pa0.x, pa0.x);
            Ash[s2][lkA0 + 1][lmA0] = pack2(pa0.y, pa0.y);
            Ash[s2][lkA0 + 2][lmA0] = pack2(pa0.z, pa0.z);
            Ash[s2][lkA0 + 3][lmA0] = pack2(pa0.w, pa0.w);
            Ash[s2][lkA1 + 0][lmA1] = pack2(pa1.x, pa1.x);
            Ash[s2][lkA1 + 1][lmA1] = pack2(pa1.y, pa1.y);
            Ash[s2][lkA1 + 2][lmA1] = pack2(pa1.z, pa1.z);
            Ash[s2][lkA1 + 3][lmA1] = pack2(pa1.w, pa1.w);
            *(float4*)&Bsh[s2][lkB][lnB] = pb;
            __syncthreads();
        }
        s ^= 1;
    }

#pragma unroll
    for (int i = 0; i < 8; i++) {
        float* cp = C + (size_t)(m0 + tm * 8 + i) * GSZ + n0 + tn * 4;
        ulonglong2 sv; sv.x = acc[i][0]; sv.y = acc[i][1];
        *(ulonglong2*)cp = sv;
    }
}

// ---------------------------------------------------------------------------
// Recurrence: persistent, 128 CTAs x 256 threads (8 warps).
// CTA owns 8 hidden cols -> 32 gate cols. Warp w: gate pair p=w&1 (16 cols),
// K-quarter q4=w>>1 (256 k). h read directly from L2 (ldcg, coalesced per k);
// Wh slice (1024x32) SMEM-resident as ulonglong2 operands.
// ---------------------------------------------------------------------------
// smem floats: Wsh 32768 | zsh 4096 | csh 256 | hown 256 | len 32
#define REC_SMEM_FLOATS (32768 + 4096 + 256 + 256 + 32)
#define REC_SMEM_BYTES  (REC_SMEM_FLOATS * 4)

__device__ __forceinline__ void grid_sync(unsigned target)
{
    __syncthreads();
    if (threadIdx.x == 0) {
        asm volatile("red.release.gpu.global.add.u32 [%0], %1;"
                     :: "l"(&g_bar), "r"(1u) : "memory");
        unsigned v;
        do {
            asm volatile("ld.acquire.gpu.global.u32 %0, [%1];"
                         : "=r"(v) : "l"(&g_bar) : "memory");
        } while (v < target);
    }
    __syncthreads();
}

__global__ void __launch_bounds__(256) rec_kernel(
    const float* __restrict__ xproj,   // [16384,4096] (bias already added)
    const float* __restrict__ W,       // [2048,4096]; rows 1024.. are Wh
    const int*   __restrict__ lengths, // [32]
    float*       __restrict__ out_h,   // [32,512,1024]
    float*       __restrict__ hc_final)// null, or [h1 | c1]
{
    extern __shared__ __align__(16) float sm[];
    float* Wsh   = sm;                   // [k][j], j = q*8+jh, 1024*32
    float* zsh   = Wsh + 32768;          // [q][q4][b*8+jh] partials, 4*4*256
    float* csh   = zsh + 4096;           // [b*8+jh]
    float* hown  = csh + 256;
    int*   lensh = (int*)(hown + 256);

    const int tid = threadIdx.x;
    const int blk = blockIdx.x;
    const int b   = tid & 31;
    const int w   = tid >> 5;            // 0..7
    const int p   = w & 1;               // gate pair: gates 2p, 2p+1
    const int q4  = w >> 1;              // K-quarter 0..3

    // Wh slice into smem: Wsh[k][q*8+jh] = W[1024+k][q*1024 + blk*8 + jh]
    for (int i = tid; i < 32768; i += 256) {
        int k = i >> 5, j = i & 31;
        int qq = j >> 3, jh = j & 7;
        Wsh[i] = W[(size_t)(HS + k) * GSZ + qq * HS + blk * 8 + jh];
    }
    if (tid < 32) lensh[tid] = lengths[tid];
    csh[tid] = 0.0f; hown[tid] = 0.0f;
    g_hbuf[blk * 256 + tid] = 0.0f;      // zero ping buffer 0 slice

    unsigned bar_t = NBLK;
    grid_sync(bar_t);

    int cur = 0;
    const ulonglong2* Wsh2 = (const ulonglong2*)Wsh;

    for (int t = 0; t < TSTEP; t++) {
        // hoisted xproj loads (consumed ~8k cycles later -> latency hidden)
        ulonglong2 xv0, xv1, xv2, xv3;
        if (q4 == 0) {
            const float* xp = xproj + ((size_t)(b * TSTEP + t)) * GSZ + blk * 8;
            xv0 = *(const ulonglong2*)(xp + (2 * p)     * HS);
            xv1 = *(const ulonglong2*)(xp + (2 * p)     * HS + 4);
            xv2 = *(const ulonglong2*)(xp + (2 * p + 1) * HS);
            xv3 = *(const ulonglong2*)(xp + (2 * p + 1) * HS + 4);
        }

        u64 acc[8];
#pragma unroll
        for (int i = 0; i < 8; i++) acc[i] = 0ull;

        // gate GEMM over this warp's K-quarter, h straight from L2
        {
            const float* hsrc = g_hbuf + (size_t)cur * 32768 + q4 * 8192 + b;
            const ulonglong2* Wr = Wsh2 + (size_t)(q4 * 256) * 8 + p * 4;
#pragma unroll 8
            for (int kk = 0; kk < 256; kk++) {
                float hv = __ldcg(hsrc + kk * 32);
                u64 h2 = pack2(hv, hv);
                ulonglong2 wA = Wr[kk * 8];
                ulonglong2 wB = Wr[kk * 8 + 1];
                ulonglong2 wC = Wr[kk * 8 + 2];
                ulonglong2 wD = Wr[kk * 8 + 3];
                acc[0] = ffma2(h2, wA.x, acc[0]);
                acc[1] = ffma2(h2, wA.y, acc[1]);
                acc[2] = ffma2(h2, wB.x, acc[2]);
                acc[3] = ffma2(h2, wB.y, acc[3]);
                acc[4] = ffma2(h2, wC.x, acc[4]);
                acc[5] = ffma2(h2, wC.y, acc[5]);
                acc[6] = ffma2(h2, wD.x, acc[6]);
                acc[7] = ffma2(h2, wD.y, acc[7]);
            }
        }

        // fold x into quarter-0 partials
        if (q4 == 0) {
            acc[0] = add2(acc[0], xv0.x); acc[1] = add2(acc[1], xv0.y);
            acc[2] = add2(acc[2], xv1.x); acc[3] = add2(acc[3], xv1.y);
            acc[4] = add2(acc[4], xv2.x); acc[5] = add2(acc[5], xv2.y);
            acc[6] = add2(acc[6], xv3.x); acc[7] = add2(acc[7], xv3.y);
        }

        // store partials: zsh[q][q4][b][jh]
        {
            u64* z64 = (u64*)zsh;
#pragma unroll
            for (int gi = 0; gi < 2; gi++) {
                int g = 2 * p + gi;
                u64* dstz = z64 + ((g * 1024 + q4 * 256 + b * 8) >> 1);
                dstz[0] = acc[gi * 4 + 0];
                dstz[1] = acc[gi * 4 + 1];
                dstz[2] = acc[gi * 4 + 2];
                dstz[3] = acc[gi * 4 + 3];
            }
        }
        __syncthreads();

        // cell update: 256 units, one per thread
        const int nxt = cur ^ 1;
        {
            int u  = tid;
            int bu = u >> 3, jh = u & 7;
            float zq[4];
#pragma unroll
            for (int g = 0; g < 4; g++) {
                zq[g] = zsh[g * 1024 + u] + zsh[g * 1024 + 256 + u]
                      + zsh[g * 1024 + 512 + u] + zsh[g * 1024 + 768 + u];
            }
            float cp = csh[u];
            float cn = sigf(zq[2] + 1.0f) * cp + sigf(zq[0]) * tanhf(zq[1]);
            float hn = sigf(zq[3]) * tanhf(cn);
            bool mask = (t < lensh[bu]);
            float hk = mask ? hn : hown[u];
            float ck = mask ? cn : cp;
            csh[u]  = ck;
            hown[u] = hk;
            int kg = blk * 8 + jh;
            out_h[((size_t)bu * TSTEP + t) * HS + kg] = mask ? hn : 0.0f;
            __stcg(&g_hbuf[(size_t)nxt * 32768 + kg * 32 + bu], hk);
            if (hc_final != nullptr && t == TSTEP - 1) {
                hc_final[(size_t)bu * HS + kg]         = hk;
                hc_final[32768 + (size_t)bu * HS + kg] = ck;
            }
        }

        bar_t += NBLK;
        grid_sync(bar_t);
        cur = nxt;
    }
}

// ---------------------------------------------------------------------------
extern "C" void kernel_launch(void* const* d_in, const int* in_sizes, int n_in,
                              void* d_out, int out_size)
{
    const float* x       = (const float*)d_in[0];
    const int*   lengths = (const int*)  d_in[1];
    const float* W0      = (const float*)d_in[2];
    const float* b0      = (const float*)d_in[3];
    const float* W1      = (const float*)d_in[4];
    const float* b1      = (const float*)d_in[5];
    float*       out     = (float*)d_out;

    (void)in_sizes; (void)n_in; (void)out_size;

    cudaFuncSetAttribute(rec_kernel,
                         cudaFuncAttributeMaxDynamicSharedMemorySize,
                         REC_SMEM_BYTES);

    float* xproj = nullptr;
    float* out0  = nullptr;
    cudaGetSymbolAddress((void**)&xproj, g_xproj);
    cudaGetSymbolAddress((void**)&out0,  g_out0);

    dim3 ggrid(GSZ / GBN, MROWS / GBM);  // (64, 128)

    // Layer 0
    gemm_kernel<<<ggrid, 256>>>(x, W0, b0, xproj);
    init_bar_kernel<<<1, 1>>>();
    rec_kernel<<<NBLK, 256, REC_SMEM_BYTES>>>(xproj, W0, lengths, out0, nullptr);

    // Layer 1
    gemm_kernel<<<ggrid, 256>>>(out0, W1, b1, xproj);
    init_bar_kernel<<<1, 1>>>();
    rec_kernel<<<NBLK, 256, REC_SMEM_BYTES>>>(xproj, W1, lengths,
                                              out, out + (size_t)MROWS * HS);
}

// round 5
// speedup vs baseline: 2.0468x; 2.0468x over previous
#include <cuda_runtime.h>
#include <cuda_bf16.h>
#include <cstddef>

// ---------------------------------------------------------------------------
// 2-layer TF LSTM: B=32, T=512, INSZ=HSZ=1024, G=4096.
// Output: concat(out1[32,512,1024], h1[32,1024], c1[32,1024]) f32.
// ---------------------------------------------------------------------------

#define BSZ   32
#define TSTEP 512
#define HS    1024
#define GSZ   4096
#define MROWS (BSZ * TSTEP)      // 16384
#define NBLK  128                // persistent CTAs for recurrence

typedef unsigned long long u64;

// ----------------------------- device scratch ------------------------------
__device__ __align__(16) float g_xproj[(size_t)MROWS * GSZ];  // 256 MB
__device__ __align__(16) float g_out0 [(size_t)MROWS * HS];   //  64 MB
__device__ __align__(16) float g_hbuf [2 * HS * BSZ];         // ping-pong h, [buf][k][b]
__device__ unsigned g_bar;

// ----------------------------- f32x2 helpers -------------------------------
__device__ __forceinline__ u64 pack2(float lo, float hi) {
    u64 r; asm("mov.b64 %0, {%1, %2};" : "=l"(r) : "f"(lo), "f"(hi)); return r;
}
__device__ __forceinline__ void unpack2(u64 v, float& lo, float& hi) {
    asm("mov.b64 {%0, %1}, %2;" : "=f"(lo), "=f"(hi) : "l"(v));
}
__device__ __forceinline__ u64 ffma2(u64 a, u64 b, u64 c) {
    u64 d; asm("fma.rn.f32x2 %0, %1, %2, %3;" : "=l"(d) : "l"(a), "l"(b), "l"(c)); return d;
}
__device__ __forceinline__ u64 add2(u64 a, u64 b) {
    u64 d; asm("add.rn.f32x2 %0, %1, %2;" : "=l"(d) : "l"(a), "l"(b)); return d;
}
__device__ __forceinline__ float sigf(float x) { return 1.0f / (1.0f + __expf(-x)); }

// ----------------------------- barrier reset -------------------------------
__global__ void init_bar_kernel() { g_bar = 0u; }

// ---------------------------------------------------------------------------
// GEMM (R2 config, measured fma=66.6%): C = A[.,0:1024] @ W[0:1024,.] + bias
// Tile 128(m) x 64(n), BK=16, 256 threads, microtile 8x4 with f32x2 pairs.
// ---------------------------------------------------------------------------
#define GBM 128
#define GBN 64
#define GBK 16

__global__ void __launch_bounds__(256) gemm_kernel(
    const float* __restrict__ A, const float* __restrict__ W,
    const float* __restrict__ bias, float* __restrict__ C)
{
    __shared__ float Ash[GBK][132];
    __shared__ __align__(16) float Bsh[GBK][GBN];

    const int tid = threadIdx.x;
    const int m0  = blockIdx.y * GBM;
    const int n0  = blockIdx.x * GBN;
    const int tm  = tid >> 4;
    const int tn  = tid & 15;

    u64 acc[8][2];
    {
        float4 bv = *(const float4*)(bias + n0 + tn * 4);
        u64 b01 = pack2(bv.x, bv.y), b23 = pack2(bv.z, bv.w);
#pragma unroll
        for (int i = 0; i < 8; i++) { acc[i][0] = b01; acc[i][1] = b23; }
    }

    for (int k0 = 0; k0 < HS; k0 += GBK) {
#pragma unroll
        for (int r = 0; r < 2; r++) {
            int f = tid + r * 256;
            int m = f >> 2, kq = (f & 3) * 4;
            float4 av = *(const float4*)(A + (size_t)(m0 + m) * HS + k0 + kq);
            Ash[kq + 0][m] = av.x; Ash[kq + 1][m] = av.y;
            Ash[kq + 2][m] = av.z; Ash[kq + 3][m] = av.w;
        }
        {
            int k = tid >> 4, n4 = (tid & 15) * 4;
            *(float4*)&Bsh[k][n4] =
                *(const float4*)(W + (size_t)(k0 + k) * GSZ + n0 + n4);
        }
        __syncthreads();

#pragma unroll
        for (int kk = 0; kk < GBK; kk++) {
            float4 a0 = *(const float4*)&Ash[kk][tm * 8];
            float4 a1 = *(const float4*)&Ash[kk][tm * 8 + 4];
            float4 b4 = *(const float4*)&Bsh[kk][tn * 4];
            u64 w01 = pack2(b4.x, b4.y), w23 = pack2(b4.z, b4.w);
            float am[8] = {a0.x, a0.y, a0.z, a0.w, a1.x, a1.y, a1.z, a1.w};
#pragma unroll
            for (int i = 0; i < 8; i++) {
                u64 ai = pack2(am[i], am[i]);
                acc[i][0] = ffma2(ai, w01, acc[i][0]);
                acc[i][1] = ffma2(ai, w23, acc[i][1]);
            }
        }
        __syncthreads();
    }

#pragma unroll
    for (int i = 0; i < 8; i++) {
        float x0, x1, x2, x3;
        unpack2(acc[i][0], x0, x1);
        unpack2(acc[i][1], x2, x3);
        *(float4*)(C + (size_t)(m0 + tm * 8 + i) * GSZ + n0 + tn * 4) =
            make_float4(x0, x1, x2, x3);
    }
}

// ---------------------------------------------------------------------------
// Recurrence: persistent, 128 CTAs x 256 threads (8 warps).
// CTA owns 8 hidden cols -> 32 gate cols. Warp w: gate pair p=w&1 (16 cols),
// k-subchunk k64=w>>1 (64 k within the active quarter).
// Per step: 4 phases over K-quarters; quarter q+1 is loaded from L2 into
// registers while computing quarter q, stored to the other hsh buffer at
// phase end (double-buffered staging -> stage latency hidden).
// ---------------------------------------------------------------------------
// smem floats: Wsh 32768 | hsh 2*8192 | zsh 4096 | csh 256 | hown 256 | len 32
#define REC_SMEM_FLOATS (32768 + 16384 + 4096 + 256 + 256 + 32)
#define REC_SMEM_BYTES  (REC_SMEM_FLOATS * 4)

__device__ __forceinline__ void grid_sync(unsigned target)
{
    __syncthreads();
    if (threadIdx.x == 0) {
        asm volatile("red.release.gpu.global.add.u32 [%0], %1;"
                     :: "l"(&g_bar), "r"(1u) : "memory");
        unsigned v;
        do {
            asm volatile("ld.acquire.gpu.global.u32 %0, [%1];"
                         : "=r"(v) : "l"(&g_bar) : "memory");
        } while (v < target);
    }
    __syncthreads();
}

__global__ void __launch_bounds__(256) rec_kernel(
    const float* __restrict__ xproj,   // [16384,4096] (bias already added)
    const float* __restrict__ W,       // [2048,4096]; rows 1024.. are Wh
    const int*   __restrict__ lengths, // [32]
    float*       __restrict__ out_h,   // [32,512,1024]
    float*       __restrict__ hc_final)// null, or [h1 | c1]
{
    extern __shared__ __align__(16) float sm[];
    float* Wsh   = sm;                   // [k][j], j = g*8+jh, 1024*32
    float* hsh   = Wsh + 32768;          // 2 buffers x [kk<256][b]
    float* zsh   = hsh + 16384;          // [g][k64][b*8+jh], 4*4*256
    float* csh   = zsh + 4096;
    float* hown  = csh + 256;
    int*   lensh = (int*)(hown + 256);

    const int tid = threadIdx.x;
    const int blk = blockIdx.x;
    const int b   = tid & 31;
    const int w   = tid >> 5;            // 0..7
    const int p   = w & 1;               // gate pair: gates 2p, 2p+1
    const int k64 = w >> 1;              // k-subchunk within quarter, 0..3

    for (int i = tid; i < 32768; i += 256) {
        int k = i >> 5, j = i & 31;
        int qq = j >> 3, jh = j & 7;
        Wsh[i] = W[(size_t)(HS + k) * GSZ + qq * HS + blk * 8 + jh];
    }
    if (tid < 32) lensh[tid] = lengths[tid];
    csh[tid] = 0.0f; hown[tid] = 0.0f;
    g_hbuf[blk * 256 + tid] = 0.0f;

    unsigned bar_t = NBLK;
    grid_sync(bar_t);

    int cur = 0;
    const ulonglong2* Wsh2 = (const ulonglong2*)Wsh;

    for (int t = 0; t < TSTEP; t++) {
        const float4* hq = (const float4*)(g_hbuf + (size_t)cur * 32768);
        float4* hsh4 = (float4*)hsh;

        // hoisted xproj loads (consumed ~8k cycles later)
        ulonglong2 xv0, xv1, xv2, xv3;
        if (k64 == 0) {
            const float* xp = xproj + ((size_t)(b * TSTEP + t)) * GSZ + blk * 8;
            xv0 = *(const ulonglong2*)(xp + (2 * p)     * HS);
            xv1 = *(const ulonglong2*)(xp + (2 * p)     * HS + 4);
            xv2 = *(const ulonglong2*)(xp + (2 * p + 1) * HS);
            xv3 = *(const ulonglong2*)(xp + (2 * p + 1) * HS + 4);
        }

        // stage quarter 0 into buffer 0
#pragma unroll
        for (int r = 0; r < 8; r++)
            hsh4[tid + r * 256] = __ldcg(hq + tid + r * 256);
        __syncthreads();

        u64 acc[8];
#pragma unroll
        for (int i = 0; i < 8; i++) acc[i] = 0ull;

#pragma unroll
        for (int q = 0; q < 4; q++) {
            const int buf = q & 1;

            // prefetch quarter q+1 into registers (overlaps with compute)
            float4 stg[8];
            if (q < 3) {
#pragma unroll
                for (int r = 0; r < 8; r++)
                    stg[r] = __ldcg(hq + (q + 1) * 2048 + tid + r * 256);
            }

            // compute on quarter q: this warp's 64-k subchunk, 16 gate cols
            const float* hb = hsh + buf * 8192 + k64 * 64 * 32 + b;
            const ulonglong2* Wr =
                Wsh2 + (size_t)(q * 256 + k64 * 64) * 8 + p * 4;
#pragma unroll 16
            for (int kk = 0; kk < 64; kk++) {
                float hv = hb[kk * 32];
                u64 h2 = pack2(hv, hv);
                ulonglong2 wA = Wr[kk * 8];
                ulonglong2 wB = Wr[kk * 8 + 1];
                ulonglong2 wC = Wr[kk * 8 + 2];
                ulonglong2 wD = Wr[kk * 8 + 3];
                acc[0] = ffma2(h2, wA.x, acc[0]);
                acc[1] = ffma2(h2, wA.y, acc[1]);
                acc[2] = ffma2(h2, wB.x, acc[2]);
                acc[3] = ffma2(h2, wB.y, acc[3]);
                acc[4] = ffma2(h2, wC.x, acc[4]);
                acc[5] = ffma2(h2, wC.y, acc[5]);
                acc[6] = ffma2(h2, wD.x, acc[6]);
                acc[7] = ffma2(h2, wD.y, acc[7]);
            }

            if (q < 3) {
                float4* dstb = (float4*)(hsh + (buf ^ 1) * 8192);
#pragma unroll
                for (int r = 0; r < 8; r++)
                    dstb[tid + r * 256] = stg[r];
                __syncthreads();
            }
        }

        // fold x into k64==0 partials
        if (k64 == 0) {
            acc[0] = add2(acc[0], xv0.x); acc[1] = add2(acc[1], xv0.y);
            acc[2] = add2(acc[2], xv1.x); acc[3] = add2(acc[3], xv1.y);
            acc[4] = add2(acc[4], xv2.x); acc[5] = add2(acc[5], xv2.y);
            acc[6] = add2(acc[6], xv3.x); acc[7] = add2(acc[7], xv3.y);
        }

        // store partials: zsh[g][k64][b][jh]
        {
            u64* z64 = (u64*)zsh;
#pragma unroll
            for (int gi = 0; gi < 2; gi++) {
                int g = 2 * p + gi;
                u64* dstz = z64 + ((g * 1024 + k64 * 256 + b * 8) >> 1);
                dstz[0] = acc[gi * 4 + 0];
                dstz[1] = acc[gi * 4 + 1];
                dstz[2] = acc[gi * 4 + 2];
                dstz[3] = acc[gi * 4 + 3];
            }
        }
        __syncthreads();

        // cell update: 256 units, one per thread
        const int nxt = cur ^ 1;
        {
            int u  = tid;
            int bu = u >> 3, jh = u & 7;
            float zq[4];
#pragma unroll
            for (int g = 0; g < 4; g++) {
                zq[g] = zsh[g * 1024 + u] + zsh[g * 1024 + 256 + u]
                      + zsh[g * 1024 + 512 + u] + zsh[g * 1024 + 768 + u];
            }
            float cp = csh[u];
            float cn = sigf(zq[2] + 1.0f) * cp + sigf(zq[0]) * tanhf(zq[1]);
            float hn = sigf(zq[3]) * tanhf(cn);
            bool mask = (t < lensh[bu]);
            float hk = mask ? hn : hown[u];
            float ck = mask ? cn : cp;
            csh[u]  = ck;
            hown[u] = hk;
            int kg = blk * 8 + jh;
            out_h[((size_t)bu * TSTEP + t) * HS + kg] = mask ? hn : 0.0f;
            __stcg(&g_hbuf[(size_t)nxt * 32768 + kg * 32 + bu], hk);
            if (hc_final != nullptr && t == TSTEP - 1) {
                hc_final[(size_t)bu * HS + kg]         = hk;
                hc_final[32768 + (size_t)bu * HS + kg] = ck;
            }
        }

        bar_t += NBLK;
        grid_sync(bar_t);
        cur = nxt;
    }
}

// ---------------------------------------------------------------------------
extern "C" void kernel_launch(void* const* d_in, const int* in_sizes, int n_in,
                              void* d_out, int out_size)
{
    const float* x       = (const float*)d_in[0];
    const int*   lengths = (const int*)  d_in[1];
    const float* W0      = (const float*)d_in[2];
    const float* b0      = (const float*)d_in[3];
    const float* W1      = (const float*)d_in[4];
    const float* b1      = (const float*)d_in[5];
    float*       out     = (float*)d_out;

    (void)in_sizes; (void)n_in; (void)out_size;

    cudaFuncSetAttribute(rec_kernel,
                         cudaFuncAttributeMaxDynamicSharedMemorySize,
                         REC_SMEM_BYTES);

    float* xproj = nullptr;
    float* out0  = nullptr;
    cudaGetSymbolAddress((void**)&xproj, g_xproj);
    cudaGetSymbolAddress((void**)&out0,  g_out0);

    dim3 ggrid(GSZ / GBN, MROWS / GBM);  // (64, 128)

    // Layer 0
    gemm_kernel<<<ggrid, 256>>>(x, W0, b0, xproj);
    init_bar_kernel<<<1, 1>>>();
    rec_kernel<<<NBLK, 256, REC_SMEM_BYTES>>>(xproj, W0, lengths, out0, nullptr);

    // Layer 1
    gemm_kernel<<<ggrid, 256>>>(out0, W1, b1, xproj);
    init_bar_kernel<<<1, 1>>>();
    rec_kernel<<<NBLK, 256, REC_SMEM_BYTES>>>(xproj, W1, lengths,
                                              out, out + (size_t)MROWS * HS);
}